// round 15
// baseline (speedup 1.0000x reference)
#include <cuda_runtime.h>
#include <cstdint>

// Problem dims (fixed by the dataset's setup_inputs)
#define C_   128
#define H_   56
#define W_   56
#define HW_  3136
#define TOTAL_ (16 * 128 * 3136)

#define NQUAD_TOT (TOTAL_ / 4)    // 1,605,632 quads (4 horizontal px each)
#define TPB 256

// set.ge -> -1 (true) / 0 (false): single SASS FSET, no predication
__device__ __forceinline__ int setge(float a, float b) {
    int r;
    asm("set.ge.s32.f32 %0, %1, %2;" : "=r"(r) : "f"(a), "f"(b));
    return r;
}

// ---- nibble-packed rank counters, 4 windows (see round-11 proof) -----------
// Counter id = w*9 + e (0..35), nibble id&7 of word id>>3 (5 words).
// Init = 8 - e; every prefix stays in [0,8] -> nibbles never carry/borrow.
__host__ __device__ constexpr int nibK(int wi, int w, int r, int c) {
    int id = w * 9 + (3 * r + c - w);
    return ((id >> 3) == wi) ? (1 << (4 * (id & 7))) : 0;
}
__host__ __device__ constexpr int kpair(int wi, int rX, int cX, int rY, int cY) {
    int s = 0;
    for (int w = 0; w < 4; w++)
        if (cX >= w && cX <= w + 2 && cY >= w && cY <= w + 2)
            s += nibK(wi, w, rX, cX) - nibK(wi, w, rY, cY);
    return s;
}
__host__ __device__ constexpr int initw(int wi) {
    int v = 0;
    for (int id = wi * 8; id < wi * 8 + 8 && id < 36; id++)
        v |= (8 - (id % 9)) << (4 * (id & 7));
    return v;
}

#define PAIR(rX, cX, rY, cY)                                                  \
    {                                                                         \
        const int m = setge(v[rX][cX], v[rY][cY]);                            \
        { constexpr int K = kpair(0, rX, cX, rY, cY); if (K) w0 += m * K; }   \
        { constexpr int K = kpair(1, rX, cX, rY, cY); if (K) w1 += m * K; }   \
        { constexpr int K = kpair(2, rX, cX, rY, cY); if (K) w2 += m * K; }   \
        { constexpr int K = kpair(3, rX, cX, rY, cY); if (K) w3 += m * K; }   \
        { constexpr int K = kpair(4, rX, cX, rY, cY); if (K) w4 += m * K; }   \
    }

#define WROW(r)                                                               \
    PAIR(r,0,r,1) PAIR(r,0,r,2) PAIR(r,1,r,2) PAIR(r,1,r,3) PAIR(r,2,r,3)     \
    PAIR(r,2,r,4) PAIR(r,3,r,4) PAIR(r,3,r,5) PAIR(r,4,r,5)
#define XROW(ra, rb)                                                          \
    PAIR(ra,0,rb,0) PAIR(ra,0,rb,1) PAIR(ra,0,rb,2)                           \
    PAIR(ra,1,rb,0) PAIR(ra,1,rb,1) PAIR(ra,1,rb,2) PAIR(ra,1,rb,3)           \
    PAIR(ra,2,rb,0) PAIR(ra,2,rb,1) PAIR(ra,2,rb,2) PAIR(ra,2,rb,3)           \
    PAIR(ra,2,rb,4)                                                           \
    PAIR(ra,3,rb,1) PAIR(ra,3,rb,2) PAIR(ra,3,rb,3) PAIR(ra,3,rb,4)           \
    PAIR(ra,3,rb,5)                                                           \
    PAIR(ra,4,rb,2) PAIR(ra,4,rb,3) PAIR(ra,4,rb,4) PAIR(ra,4,rb,5)           \
    PAIR(ra,5,rb,3) PAIR(ra,5,rb,4) PAIR(ra,5,rb,5)

// rank extraction — w/e become literals after unroll; selector folds
#define WSEL_(i) ((i)==0 ? w0 : (i)==1 ? w1 : (i)==2 ? w2 : (i)==3 ? w3 : w4)
#define RANK_(w, e) ((WSEL_(((w)*9+(e)) >> 3) >> (4 * (((w)*9+(e)) & 7))) & 15)

// one window: value accumulate + byte index scatter (w literal)
#define DOWIN(w, out)                                                            \
    {                                                                            \
        float acc = 0.f;                                                         \
        int q;                                                                   \
        q = RANK_(w,0); acc = fmaf(v[0][(w)+0], tb[q], acc); st[9*(w)+q] = 0;    \
        q = RANK_(w,1); acc = fmaf(v[0][(w)+1], tb[q], acc); st[9*(w)+q] = 1;    \
        q = RANK_(w,2); acc = fmaf(v[0][(w)+2], tb[q], acc); st[9*(w)+q] = 2;    \
        q = RANK_(w,3); acc = fmaf(v[1][(w)+0], tb[q], acc); st[9*(w)+q] = 3;    \
        q = RANK_(w,4); acc = fmaf(v[1][(w)+1], tb[q], acc); st[9*(w)+q] = 4;    \
        q = RANK_(w,5); acc = fmaf(v[1][(w)+2], tb[q], acc); st[9*(w)+q] = 5;    \
        q = RANK_(w,6); acc = fmaf(v[2][(w)+0], tb[q], acc); st[9*(w)+q] = 6;    \
        q = RANK_(w,7); acc = fmaf(v[2][(w)+1], tb[q], acc); st[9*(w)+q] = 7;    \
        q = RANK_(w,8); acc = fmaf(v[2][(w)+2], tb[q], acc); st[9*(w)+q] = 8;    \
        out = acc;                                                               \
    }

__global__ __launch_bounds__(TPB, 7)   // 7 blocks/SM: 36-reg target, occ 87.5% cap
void rrsvm_kernel(const float* __restrict__ x,
                  const float* __restrict__ s,
                  float* __restrict__ vout,
                  float* __restrict__ idxout)
{
    __shared__ float ssm[8][18];                             // 2 channels per warp
    __shared__ __align__(16) unsigned char stage8[8][1152];  // byte idx stage

    const int tid  = threadIdx.x;
    const int warp = tid >> 5;
    const int lane = tid & 31;
    const int t    = blockIdx.x * TPB + tid;            // quad id, exact grid

    const int p0  = t * 4;                              // first pixel (global)
    const int bc  = p0 / HW_;                           // b*C + c (4 | HW_)
    const int rem = p0 - bc * HW_;
    const int y   = rem / W_;
    const int xx  = rem - y * W_;                       // multiple of 4

    // Warp can straddle at most one (b,c) boundary: two-channel s table.
    const int bcf = __shfl_sync(0xFFFFFFFFu, bc, 0);
    const int bcl = __shfl_sync(0xFFFFFFFFu, bc, 31);
    if (lane < 9)
        ssm[warp][lane] = __ldg(s + (bcf & (C_ - 1)) * 9 + lane);
    else if (lane < 18)
        ssm[warp][lane] = __ldg(s + (bcl & (C_ - 1)) * 9 + lane - 9);
    __syncwarp();
    const float* tb = ssm[warp] + ((bc != bcf) ? 9 : 0);

    const float* __restrict__ xb = x + (size_t)bc * HW_;

    // 3 rows x 6 cols covering the 4 windows. Interior 4 via one float4;
    // edges come from the horizontally-adjacent lane's float4 (same row,
    // same channel whenever xx>0 / xx<52 — padding zeros propagate because
    // m4 is zeroed for OOB rows). Only warp-boundary lanes do fixup loads.
    float v[3][6];
#pragma unroll
    for (int rr = 0; rr < 3; rr++) {
        const int gy   = y + rr - 1;
        const bool rok = ((unsigned)gy < (unsigned)H_);
        const float* p = xb + gy * W_ + xx;
        float4 m4 = make_float4(0.f, 0.f, 0.f, 0.f);
        if (rok) m4 = *(const float4*)p;                 // 16B aligned
        v[rr][1] = m4.x; v[rr][2] = m4.y; v[rr][3] = m4.z; v[rr][4] = m4.w;

        float left  = __shfl_up_sync(0xFFFFFFFFu, m4.w, 1);
        float right = __shfl_down_sync(0xFFFFFFFFu, m4.x, 1);
        if (lane == 0  && xx > 0)  left  = rok ? __ldg(p - 1) : 0.f;
        if (lane == 31 && xx < 52) right = rok ? __ldg(p + 4) : 0.f;
        v[rr][0] = (xx == 0)  ? 0.f : left;
        v[rr][5] = (xx == 52) ? 0.f : right;
    }

    // nibble-packed rank accumulation
    int w0 = initw(0), w1 = initw(1), w2 = initw(2), w3 = initw(3), w4 = initw(4);

    WROW(0) WROW(1) WROW(2)
    XROW(0, 1) XROW(0, 2) XROW(1, 2)

    // Values (s-gather: <=9 distinct words in distinct banks -> multicast,
    // conflict-free) + byte index scatter (36B/lane regions -> lanes occupy
    // disjoint 9-word spans, near-conflict-free).
    unsigned char* st = &stage8[warp][lane * 36];
    float a0, a1, a2, a3;
    DOWIN(0, a0)
    DOWIN(1, a1)
    DOWIN(2, a2)
    DOWIN(3, a3)

    if (vout) {
        float4 o = make_float4(a0, a1, a2, a3);
        *(float4*)(vout + (size_t)p0) = o;               // 16B aligned
    }

    __syncwarp();
    if (idxout) {
        // warp's 128 pixels = 1152 idx floats, staged as 1152 bytes = 288 u32.
        // Each u32 -> float4 via PRMT(0x4B0000|e) + FADD(-8388608): exact for
        // e in 0..8 (verified round 9). 9 conflict-free LDS.32 per lane.
        const unsigned* sw  = (const unsigned*)stage8[warp];
        float4*         dst = (float4*)(idxout + (size_t)(t - lane) * 36);
#pragma unroll
        for (int k = 0; k < 9; k++) {
            const int m = lane + 32 * k;
            const unsigned w = sw[m];
            float4 f;
            f.x = __uint_as_float(__byte_perm(w, 0x4B000000u, 0x7440)) - 8388608.f;
            f.y = __uint_as_float(__byte_perm(w, 0x4B000000u, 0x7441)) - 8388608.f;
            f.z = __uint_as_float(__byte_perm(w, 0x4B000000u, 0x7442)) - 8388608.f;
            f.w = __uint_as_float(__byte_perm(w, 0x4B000000u, 0x7443)) - 8388608.f;
            dst[m] = f;
        }
    }
}

extern "C" void kernel_launch(void* const* d_in, const int* in_sizes, int n_in,
                              void* d_out, int out_size) {
    const float* x = (const float*)d_in[0];
    const float* s = (const float*)d_in[1];

    float* vout   = (float*)d_out;
    float* idxout = nullptr;

    // Reference returns (out[B,C,H,W], indices[B,C,H,W,9]); harness concatenates.
    if (out_size >= 10 * TOTAL_) {
        idxout = (float*)d_out + TOTAL_;   // [out | indices]
    } else if (out_size == 9 * TOTAL_) {
        idxout = (float*)d_out;            // indices only
        vout   = nullptr;
    }

    const int blocks = NQUAD_TOT / TPB;    // exact: 6272
    rrsvm_kernel<<<blocks, TPB>>>(x, s, vout, idxout);
}